// round 1
// baseline (speedup 1.0000x reference)
#include <cuda_runtime.h>
#include <cstdint>
#include <cstddef>

#define NB    4
#define NSRC  16384
#define NTGT  4096
#define KNN   32
#define TPB   512
#define CHUNK 4096
#define FULLM 0xffffffffu

// Output layout (flattened concat of the reference tuple, all as float32):
//   patches      [B,NT,K,3]  : 1572864 elems @ offset 0
//   patches_idx  [B,NT,K,2]  : 1048576 elems @ offset 1572864
//   patches_size [B,NT]      :   16384 elems @ offset 2621440
//   rad          [B,1,1]     :       4 elems @ offset 2637824
//   patches_dist [B,NT,K]    :  524288 elems @ offset 2637828
#define OFF_PATCH 0
#define OFF_IDX   1572864
#define OFF_SIZE  2621440
#define OFF_RAD   2637824
#define OFF_DIST  2637828

// Scratch: packed (x,y,z,sumsq) for source and target. __device__ globals (no alloc).
__device__ float4 g_spk[NB * NSRC];
__device__ float4 g_tpk[NB * NTGT];

__global__ void prep_kernel(const float* __restrict__ src,
                            const float* __restrict__ tgt) {
    int i = blockIdx.x * blockDim.x + threadIdx.x;
    if (i < NB * NSRC) {
        float x = src[3 * i + 0], y = src[3 * i + 1], z = src[3 * i + 2];
        // sum(source*source): elementwise mul, then left-to-right add (matches jnp reduce)
        float ss = __fadd_rn(__fadd_rn(__fmul_rn(x, x), __fmul_rn(y, y)), __fmul_rn(z, z));
        g_spk[i] = make_float4(x, y, z, ss);
    }
    if (i < NB * NTGT) {
        float x = tgt[3 * i + 0], y = tgt[3 * i + 1], z = tgt[3 * i + 2];
        float tt = __fadd_rn(__fadd_rn(__fmul_rn(x, x), __fmul_rn(y, y)), __fmul_rn(z, z));
        g_tpk[i] = make_float4(x, y, z, tt);
    }
}

// One warp per target point. Warp holds the running top-32 sorted ascending
// across lanes (lane l = rank l). Sources scanned in ascending index order so
// the strict-< threshold + (<=)-position insertion reproduces top_k's
// lower-index-first tie-break exactly.
__global__ __launch_bounds__(TPB) void knn_kernel(const float* __restrict__ src,
                                                  float* __restrict__ out) {
    __shared__ float4 s_src[CHUNK];

    const int warp = threadIdx.x >> 5;
    const int lane = threadIdx.x & 31;

    // 256 blocks per batch, 16 targets (warps) per block
    const int b    = blockIdx.x >> 8;
    const int t_in = ((blockIdx.x & 255) << 4) + warp;
    const int tg   = b * NTGT + t_in;           // global target id in [0, 16384)

    const float4 T = g_tpk[tg];
    const float tx = T.x, ty = T.y, tz = T.z, tt = T.w;

    const float INF = __int_as_float(0x7f800000);
    float lv = INF;   // this lane's list value (rank = lane)
    int   li = -1;    // this lane's list index
    float thr = INF;  // current K-th smallest (lane 31's value), replicated

    const float4* sb = g_spk + b * NSRC;

    for (int c = 0; c < NSRC; c += CHUNK) {
        __syncthreads();
        #pragma unroll
        for (int i = threadIdx.x; i < CHUNK; i += TPB) s_src[i] = sb[c + i];
        __syncthreads();

        #pragma unroll 4
        for (int it = 0; it < CHUNK / 32; ++it) {
            const float4 S = s_src[it * 32 + lane];
            // dot: FMA accumulation chain k=0,1,2 (cuBLAS/Eigen style)
            float dot = __fmaf_rn(tz, S.z, __fmaf_rn(ty, S.y, __fmul_rn(tx, S.x)));
            // sq = (tt - 2*dot) + ss, each op individually rounded
            float sq  = __fadd_rn(__fsub_rn(tt, __fmul_rn(2.0f, dot)), S.w);

            unsigned ball = __ballot_sync(FULLM, sq < thr);
            if (ball) {
                const int j = c + it * 32 + lane;
                do {
                    const int   sl = __ffs(ball) - 1;
                    ball &= ball - 1;
                    const float nv = __shfl_sync(FULLM, sq, sl);
                    const int   nj = __shfl_sync(FULLM, j,  sl);
                    // insertion position: count of entries <= nv (equal keeps lower idx first)
                    const unsigned le = __ballot_sync(FULLM, lv <= nv);
                    const int pos = __popc(le);
                    if (pos < 32) {
                        const float pv = __shfl_up_sync(FULLM, lv, 1);
                        const int   pj = __shfl_up_sync(FULLM, li, 1);
                        if (lane > pos)       { lv = pv; li = pj; }
                        else if (lane == pos) { lv = nv; li = nj; }
                    }
                } while (ball);
                thr = __shfl_sync(FULLM, lv, 31);
            }
        }
    }

    // ---- outputs ----
    const float rad  = 0.2f;
    const float rad2 = __fmul_rn(rad, rad);
    const bool  mask = (rad2 >= lv);

    // gather scaled source coords (0 if masked), center on scaled target
    float gx = 0.0f, gy = 0.0f, gz = 0.0f;
    if (mask) {
        const float* sp = src + (size_t)(b * NSRC + li) * 3;
        gx = __fdiv_rn(sp[0], rad);
        gy = __fdiv_rn(sp[1], rad);
        gz = __fdiv_rn(sp[2], rad);
    }
    const float tdx = __fdiv_rn(tx, rad);
    const float tdy = __fdiv_rn(ty, rad);
    const float tdz = __fdiv_rn(tz, rad);

    const size_t e = (size_t)tg * KNN + lane;

    float* patches = out + OFF_PATCH;
    patches[3 * e + 0] = __fsub_rn(gx, tdx);
    patches[3 * e + 1] = __fsub_rn(gy, tdy);
    patches[3 * e + 2] = __fsub_rn(gz, tdz);

    float* idxf = out + OFF_IDX;
    idxf[2 * e + 0] = (float)b;
    idxf[2 * e + 1] = (float)(mask ? li : -1);

    float* pdist = out + OFF_DIST;
    pdist[e] = __fdiv_rn(__fsqrt_rn(fmaxf(lv, 1e-9f)), rad);

    const unsigned mball = __ballot_sync(FULLM, mask);
    if (lane == 0) {
        float* psize = out + OFF_SIZE;
        psize[tg] = (float)__popc(mball);
    }

    if (blockIdx.x == 0 && threadIdx.x < NB) {
        float* prad = out + OFF_RAD;
        prad[threadIdx.x] = rad;
    }
}

extern "C" void kernel_launch(void* const* d_in, const int* in_sizes, int n_in,
                              void* d_out, int out_size) {
    // metadata order: source [4,16384,3], target [4,4096,3]; swap defensively by size
    const float* src = (const float*)d_in[0];
    const float* tgt = (const float*)d_in[1];
    if (n_in >= 2 && in_sizes[0] == NB * NTGT * 3 && in_sizes[1] == NB * NSRC * 3) {
        src = (const float*)d_in[1];
        tgt = (const float*)d_in[0];
    }
    float* out = (float*)d_out;

    prep_kernel<<<(NB * NSRC + 255) / 256, 256>>>(src, tgt);
    knn_kernel<<<NB * (NTGT / 16), TPB>>>(src, out);
}